// round 13
// baseline (speedup 1.0000x reference)
#include <cuda_runtime.h>
#include <cuda_bf16.h>
#include <cstdint>

#define U_N 4096
#define I_N 8192
#define ROWS_T 12288
#define PITCHB 144                     // bytes per SMEM row (72 bf16)
#define ATILE (64 * PITCHB)            // 9216 B (64 rows x 64 k)
#define BTILE (128 * PITCHB)           // 18432 B (128 n x 64 k)
#define OFF_A0 0
#define OFF_A1 ATILE
#define OFF_B0 (2 * ATILE)
#define OFF_B1 (2 * ATILE + BTILE)
#define GSMEM_TOTAL (2 * ATILE + 2 * BTILE)   // 55296 B -> 2+ CTAs/SM

// ---------------- static device scratch (no runtime allocation) ----------------
__device__ __align__(256) uint32_t g_bitsUI[(size_t)U_N * 256]; // [u][i/32]
__device__ __align__(256) uint32_t g_bitsIU[(size_t)I_N * 128]; // [i][u/32]
__device__ float g_ru[U_N];
__device__ float g_ri[I_N];
// GEMM B operands, [n][k]: n = 2d -> hi of dim d, n = 2d+1 -> lo of dim d
__device__ __align__(256) __nv_bfloat16 g_B1[(size_t)128 * U_N]; // k = user
__device__ __align__(256) __nv_bfloat16 g_B2[(size_t)128 * I_N]; // k = item
// raw GEMM outputs, hi+lo summed in epilogue -> 64 dims
__device__ __align__(256) float g_raw1[(size_t)I_N * 64];
__device__ __align__(256) float g_raw2[(size_t)2 * U_N * 64];    // 2 K-splits
__device__ __align__(256) float g_x[(size_t)ROWS_T * 64];
__device__ __align__(256) float g_acc[(size_t)ROWS_T * 64];

// ---------------- P1: pack adjacency bits (both orientations) ----------------
__global__ __launch_bounds__(256) void pack_kernel(const int* __restrict__ edge) {
    int gw   = (blockIdx.x * 256 + threadIdx.x) >> 5;
    int lane = threadIdx.x & 31;
    int tu = gw >> 8;
    int ti = gw & 255;
    const int* base = edge + (size_t)tu * 32 * 8192 + ti * 32 + lane;
    uint32_t my = 0, uiw = 0;
    #pragma unroll 4
    for (int r = 0; r < 32; r++) {
        int val = base[(size_t)r * 8192];
        unsigned m = __ballot_sync(0xffffffffu, val != 0);
        my |= (uint32_t)(val != 0) << r;
        if (lane == r) uiw = m;
    }
    g_bitsUI[(size_t)(tu * 32 + lane) * 256 + ti] = uiw;
    g_bitsIU[(size_t)(ti * 32 + lane) * 128 + tu] = my;
}

// ---------------- P2: degrees -> rsqrt scales ----------------
__global__ __launch_bounds__(256) void scales_kernel() {
    int gw   = (blockIdx.x * 256 + threadIdx.x) >> 5;
    int lane = threadIdx.x & 31;
    int s = 0;
    if (gw < U_N) {
        const uint32_t* w = g_bitsUI + (size_t)gw * 256;
        for (int j = lane; j < 256; j += 32) s += __popc(w[j]);
        for (int o = 16; o; o >>= 1) s += __shfl_down_sync(0xffffffffu, s, o);
        if (!lane) g_ru[gw] = s ? rsqrtf((float)s) : 0.f;
    } else {
        int i = gw - U_N;
        const uint32_t* w = g_bitsIU + (size_t)i * 128;
        for (int j = lane; j < 128; j += 32) s += __popc(w[j]);
        for (int o = 16; o; o >>= 1) s += __shfl_down_sync(0xffffffffu, s, o);
        if (!lane) g_ri[i] = s ? rsqrtf((float)s) : 0.f;
    }
}

// ---------------- P3: per-layer operand prep (scale + hi/lo bf16 split) ----------
// hi -> row 2d, lo -> row 2d+1 (interleaved so epilogue sums locally)
__global__ __launch_bounds__(256) void prep_kernel(const float* __restrict__ xin, int layer) {
    __shared__ float xs[64][65];
    int b = blockIdx.x, tid = threadIdx.x;
    const float* src = (layer == 0) ? xin : g_x;
    int k0, srow, K;
    const float* sc;
    __nv_bfloat16* dst;
    if (b < 64) { k0 = b * 64;        srow = k0;         sc = g_ru; dst = g_B1; K = U_N; }
    else        { k0 = (b - 64) * 64; srow = U_N + k0;   sc = g_ri; dst = g_B2; K = I_N; }
    for (int i = tid; i < 4096; i += 256)
        xs[i >> 6][i & 63] = src[(size_t)(srow + (i >> 6)) * 64 + (i & 63)];
    __syncthreads();
    int ul = tid & 63, db = tid >> 6;
    float s = sc[k0 + ul];
    #pragma unroll
    for (int j = 0; j < 16; j++) {
        int d = db + j * 4;
        float v = s * xs[ul][d];
        __nv_bfloat16 hi = __float2bfloat16(v);
        __nv_bfloat16 lo = __float2bfloat16(v - __bfloat162float(hi));
        dst[(size_t)(2 * d) * K + k0 + ul]     = hi;
        dst[(size_t)(2 * d + 1) * K + k0 + ul] = lo;
    }
}

// ---------------- GEMM helpers ----------------
__device__ __forceinline__ void mma16816(float* c, uint32_t a0, uint32_t a1, uint32_t a2,
                                         uint32_t a3, uint32_t b0, uint32_t b1) {
    asm volatile(
        "mma.sync.aligned.m16n8k16.row.col.f32.bf16.bf16.f32 "
        "{%0,%1,%2,%3}, {%4,%5,%6,%7}, {%8,%9}, {%0,%1,%2,%3};"
        : "+f"(c[0]), "+f"(c[1]), "+f"(c[2]), "+f"(c[3])
        : "r"(a0), "r"(a1), "r"(a2), "r"(a3), "r"(b0), "r"(b1));
}
__device__ __forceinline__ void ldsm4(uint32_t* r, uint32_t addr) {
    asm volatile("ldmatrix.sync.aligned.m8n8.x4.shared.b16 {%0,%1,%2,%3}, [%4];"
                 : "=r"(r[0]), "=r"(r[1]), "=r"(r[2]), "=r"(r[3]) : "r"(addr));
}
__device__ __forceinline__ void cp16(uint32_t dst_smem, const void* src) {
    asm volatile("cp.async.cg.shared.global [%0], [%1], 16;" :: "r"(dst_smem), "l"(src));
}
__device__ __forceinline__ uint32_t smem_u32(const void* p) {
    uint32_t a;
    asm("{ .reg .u64 t; cvta.to.shared.u64 t, %1; cvt.u32.u64 %0, t; }" : "=r"(a) : "l"(p));
    return a;
}
// expand 16 adjacency bits -> 16 bf16 {0,1} (32 bytes) at dst
__device__ __forceinline__ void expand16(char* dst, uint32_t bits16) {
    uint32_t pv[8];
    #pragma unroll
    for (int p = 0; p < 8; p++) {
        uint32_t t2 = (bits16 >> (2 * p)) & 3u;
        pv[p] = ((t2 & 1u) | ((t2 & 2u) << 15)) * 0x3F80u;
    }
    *(uint4*)dst        = make_uint4(pv[0], pv[1], pv[2], pv[3]);
    *(uint4*)(dst + 16) = make_uint4(pv[4], pv[5], pv[6], pv[7]);
}

// ---------------- GEMM: M=64 tiles, 256 thr, 2+ CTAs/SM, ldmatrix + mma.sync -----
__global__ __launch_bounds__(256) void gemm_kernel() {
    extern __shared__ __align__(128) char dyn[];
    uint32_t sb = smem_u32(dyn);

    int b = blockIdx.x, tid = threadIdx.x;
    const uint32_t* bits;
    const __nv_bfloat16* Bg;
    float* raw;
    int m0, wpr, K, kbeg;
    if (b < 128) {           // dir1: top = A^T side, M=8192, K=4096
        bits = g_bitsIU; Bg = g_B1; raw = g_raw1;
        m0 = b * 64; wpr = 128; K = U_N; kbeg = 0;
    } else {                 // dir2: bot = A side, M=4096, K=8192, split-K=2
        int bb = b - 128, split = bb >> 6, mb = bb & 63;
        bits = g_bitsUI; Bg = g_B2; raw = g_raw2 + (size_t)split * U_N * 64;
        m0 = mb * 64; wpr = 256; K = I_N; kbeg = split * 4096;
    }

    int warp = tid >> 5, lane = tid & 31, g = lane >> 2, tig = lane & 3;
    int wm = warp >> 2, wn = warp & 3;           // 2x4 warp grid, 32(M) x 32(N) each

    // --- A expansion: 64 rows x 64 k; thread -> row tid>>2, 16-bit quarter tid&3
    int er = tid >> 2, eq = tid & 3;
    int esh = (eq & 1) * 16;
    const uint32_t* bitq = bits + (size_t)(m0 + er) * wpr + (kbeg >> 5) + (eq >> 1);
    int eoff = er * PITCHB + eq * 32;

    // --- B staging: 128 n x 64 k; thread covers 4 rows x 16B
    int sn0 = tid >> 3, sk0 = (tid & 7) * 8;
    const __nv_bfloat16* bsrc = Bg + (size_t)sn0 * K + kbeg + sk0;
    int bo = sn0 * PITCHB + sk0 * 2;

    // --- ldmatrix address bases per buffer
    uint32_t aAddr[2], bAddr[2];
    {
        int arow = wm * 32 + (lane & 15);
        int acol = (lane >> 4) * 8;
        int brow = wn * 32 + (lane & 7) + ((lane >> 4) & 1) * 8;
        int bcol = ((lane >> 3) & 1) * 8;
        aAddr[0] = sb + OFF_A0 + arow * PITCHB + acol * 2;
        aAddr[1] = sb + OFF_A1 + arow * PITCHB + acol * 2;
        bAddr[0] = sb + OFF_B0 + brow * PITCHB + bcol * 2;
        bAddr[1] = sb + OFF_B1 + brow * PITCHB + bcol * 2;
    }

    float c[2][4][4];
    #pragma unroll
    for (int mt = 0; mt < 2; mt++)
        #pragma unroll
        for (int tn = 0; tn < 4; tn++)
            #pragma unroll
            for (int q = 0; q < 4; q++) c[mt][tn][q] = 0.f;

    // prologue: expand A(0), stage B(0), prefetch bits(1)
    expand16(dyn + OFF_A0 + eoff, bitq[0] >> esh);
    #pragma unroll
    for (int j = 0; j < 4; j++)
        cp16(sb + OFF_B0 + bo + j * 32 * PITCHB, bsrc + (size_t)j * 32 * K);
    asm volatile("cp.async.commit_group;" ::: "memory");
    uint32_t wext = bitq[2];

    for (int ch = 0; ch < 64; ch++) {
        int cur = ch & 1, nx = cur ^ 1;
        if (ch < 63) {
            const __nv_bfloat16* src = bsrc + (size_t)(ch + 1) * 64;
            #pragma unroll
            for (int j = 0; j < 4; j++)
                cp16(sb + (nx ? OFF_B1 : OFF_B0) + bo + j * 32 * PITCHB,
                     src + (size_t)j * 32 * K);
            asm volatile("cp.async.commit_group;" ::: "memory");
            expand16(dyn + (nx ? OFF_A1 : OFF_A0) + eoff, wext >> esh);
            wext = bitq[(ch + 2 < 64) ? (ch + 2) * 2 : 0];
            asm volatile("cp.async.wait_group 1;" ::: "memory");
        } else {
            asm volatile("cp.async.wait_group 0;" ::: "memory");
        }
        __syncthreads();
        #pragma unroll
        for (int s = 0; s < 4; s++) {
            uint32_t aF[2][4], bF[2][4];
            ldsm4(aF[0], aAddr[cur] + s * 32);
            ldsm4(aF[1], aAddr[cur] + s * 32 + 16 * PITCHB);
            ldsm4(bF[0], bAddr[cur] + s * 32);
            ldsm4(bF[1], bAddr[cur] + s * 32 + 16 * PITCHB);
            #pragma unroll
            for (int mt = 0; mt < 2; mt++)
                #pragma unroll
                for (int tp = 0; tp < 2; tp++) {
                    mma16816(c[mt][2 * tp],     aF[mt][0], aF[mt][1], aF[mt][2], aF[mt][3],
                             bF[tp][0], bF[tp][1]);
                    mma16816(c[mt][2 * tp + 1], aF[mt][0], aF[mt][1], aF[mt][2], aF[mt][3],
                             bF[tp][2], bF[tp][3]);
                }
        }
        __syncthreads();
    }
    // epilogue: adjacent col pair = (hi_j, lo_j) -> sum locally, 64-wide output
    #pragma unroll
    for (int mt = 0; mt < 2; mt++)
        #pragma unroll
        for (int tn = 0; tn < 4; tn++) {
            int row0 = m0 + wm * 32 + mt * 16 + g;
            int j = wn * 16 + (tn >> 1) * 8 + (tn & 1) * 4 + tig;
            raw[(size_t)row0 * 64 + j]       = c[mt][tn][0] + c[mt][tn][1];
            raw[(size_t)(row0 + 8) * 64 + j] = c[mt][tn][2] + c[mt][tn][3];
        }
}

// ---------------- combine: split-K sum, degree scale, concat, accumulate ----------
__global__ __launch_bounds__(256) void combine_kernel(float* out, int layer) {
    int idx = blockIdx.x * 256 + threadIdx.x;  // 786432 elems
    int row = idx >> 6, d = idx & 63;
    float v;
    if (row < I_N) {
        v = g_ri[row] * g_raw1[(size_t)row * 64 + d];
    } else {
        int u = row - I_N;
        v = g_ru[u] * (g_raw2[(size_t)u * 64 + d] + g_raw2[(size_t)(U_N + u) * 64 + d]);
    }
    g_x[idx] = v;
    float a = (layer == 0) ? v : (g_acc[idx] + v);
    g_acc[idx] = a;
    if (out) out[idx] = a * 0.25f;
}

// ---------------- launch ----------------
extern "C" void kernel_launch(void* const* d_in, const int* in_sizes, int n_in,
                              void* d_out, int out_size) {
    const float* x    = (const float*)d_in[0];
    const int*   edge = (const int*)d_in[1];
    float*       out  = (float*)d_out;
    cudaFuncSetAttribute(gemm_kernel, cudaFuncAttributeMaxDynamicSharedMemorySize, GSMEM_TOTAL);
    pack_kernel<<<4096, 256>>>(edge);
    scales_kernel<<<1536, 256>>>();
    for (int l = 0; l < 3; l++) {
        prep_kernel<<<192, 256>>>(x, l);
        gemm_kernel<<<256, 256, GSMEM_TOTAL>>>();
        combine_kernel<<<3072, 256>>>(l == 2 ? out : nullptr, l);
    }
}

// round 15
// speedup vs baseline: 1.0942x; 1.0942x over previous
#include <cuda_runtime.h>
#include <cuda_bf16.h>
#include <cstdint>

#define U_N 4096
#define I_N 8192
#define ROWS_T 12288
#define PITCHB 144                     // bytes per SMEM row (72 bf16)
#define TILEB (128 * PITCHB)           // 18432 B per 128x64 bf16 tile
#define OFF_A0 0
#define OFF_A1 TILEB
#define OFF_B0 (2 * TILEB)
#define OFF_B1 (3 * TILEB)
#define GSMEM_TOTAL (4 * TILEB)        // 73728 B -> 2 CTAs/SM

// ---------------- static device scratch (no runtime allocation) ----------------
__device__ __align__(256) uint32_t g_bitsUI[(size_t)U_N * 256]; // [u][i/32]
__device__ __align__(256) uint32_t g_bitsIU[(size_t)I_N * 128]; // [i][u/32]
__device__ float g_ru[U_N];
__device__ float g_ri[I_N];
// GEMM B operands, [n][k]: n = 2d -> hi of dim d, n = 2d+1 -> lo of dim d
__device__ __align__(256) __nv_bfloat16 g_B1[(size_t)128 * U_N]; // k = user
__device__ __align__(256) __nv_bfloat16 g_B2[(size_t)128 * I_N]; // k = item
// raw GEMM outputs, hi+lo summed in epilogue -> 64 dims; split-K slices
__device__ __align__(256) float g_raw1[(size_t)2 * I_N * 64];    // 2 K-splits
__device__ __align__(256) float g_raw2[(size_t)4 * U_N * 64];    // 4 K-splits
__device__ __align__(256) float g_x[(size_t)ROWS_T * 64];
__device__ __align__(256) float g_acc[(size_t)ROWS_T * 64];

// ---------------- P1: pack adjacency bits (both orientations) ----------------
__global__ __launch_bounds__(256) void pack_kernel(const int* __restrict__ edge) {
    int gw   = (blockIdx.x * 256 + threadIdx.x) >> 5;
    int lane = threadIdx.x & 31;
    int tu = gw >> 8;
    int ti = gw & 255;
    const int* base = edge + (size_t)tu * 32 * 8192 + ti * 32 + lane;
    uint32_t my = 0, uiw = 0;
    #pragma unroll 4
    for (int r = 0; r < 32; r++) {
        int val = base[(size_t)r * 8192];
        unsigned m = __ballot_sync(0xffffffffu, val != 0);
        my |= (uint32_t)(val != 0) << r;
        if (lane == r) uiw = m;
    }
    g_bitsUI[(size_t)(tu * 32 + lane) * 256 + ti] = uiw;
    g_bitsIU[(size_t)(ti * 32 + lane) * 128 + tu] = my;
}

// ---------------- P2: degrees -> rsqrt scales ----------------
__global__ __launch_bounds__(256) void scales_kernel() {
    int gw   = (blockIdx.x * 256 + threadIdx.x) >> 5;
    int lane = threadIdx.x & 31;
    int s = 0;
    if (gw < U_N) {
        const uint32_t* w = g_bitsUI + (size_t)gw * 256;
        for (int j = lane; j < 256; j += 32) s += __popc(w[j]);
        for (int o = 16; o; o >>= 1) s += __shfl_down_sync(0xffffffffu, s, o);
        if (!lane) g_ru[gw] = s ? rsqrtf((float)s) : 0.f;
    } else {
        int i = gw - U_N;
        const uint32_t* w = g_bitsIU + (size_t)i * 128;
        for (int j = lane; j < 128; j += 32) s += __popc(w[j]);
        for (int o = 16; o; o >>= 1) s += __shfl_down_sync(0xffffffffu, s, o);
        if (!lane) g_ri[i] = s ? rsqrtf((float)s) : 0.f;
    }
}

// ---------------- P3: per-layer operand prep (scale + hi/lo bf16 split) ----------
// hi -> row 2d, lo -> row 2d+1 (interleaved so epilogue sums locally)
__global__ __launch_bounds__(256) void prep_kernel(const float* __restrict__ xin, int layer) {
    __shared__ float xs[64][65];
    int b = blockIdx.x, tid = threadIdx.x;
    const float* src = (layer == 0) ? xin : g_x;
    int k0, srow, K;
    const float* sc;
    __nv_bfloat16* dst;
    if (b < 64) { k0 = b * 64;        srow = k0;         sc = g_ru; dst = g_B1; K = U_N; }
    else        { k0 = (b - 64) * 64; srow = U_N + k0;   sc = g_ri; dst = g_B2; K = I_N; }
    for (int i = tid; i < 4096; i += 256)
        xs[i >> 6][i & 63] = src[(size_t)(srow + (i >> 6)) * 64 + (i & 63)];
    __syncthreads();
    int ul = tid & 63, db = tid >> 6;
    float s = sc[k0 + ul];
    #pragma unroll
    for (int j = 0; j < 16; j++) {
        int d = db + j * 4;
        float v = s * xs[ul][d];
        __nv_bfloat16 hi = __float2bfloat16(v);
        __nv_bfloat16 lo = __float2bfloat16(v - __bfloat162float(hi));
        dst[(size_t)(2 * d) * K + k0 + ul]     = hi;
        dst[(size_t)(2 * d + 1) * K + k0 + ul] = lo;
    }
}

// ---------------- GEMM helpers ----------------
__device__ __forceinline__ void mma16816(float* c, uint32_t a0, uint32_t a1, uint32_t a2,
                                         uint32_t a3, uint32_t b0, uint32_t b1) {
    asm volatile(
        "mma.sync.aligned.m16n8k16.row.col.f32.bf16.bf16.f32 "
        "{%0,%1,%2,%3}, {%4,%5,%6,%7}, {%8,%9}, {%0,%1,%2,%3};"
        : "+f"(c[0]), "+f"(c[1]), "+f"(c[2]), "+f"(c[3])
        : "r"(a0), "r"(a1), "r"(a2), "r"(a3), "r"(b0), "r"(b1));
}
__device__ __forceinline__ void ldsm4(uint32_t* r, uint32_t addr) {
    asm volatile("ldmatrix.sync.aligned.m8n8.x4.shared.b16 {%0,%1,%2,%3}, [%4];"
                 : "=r"(r[0]), "=r"(r[1]), "=r"(r[2]), "=r"(r[3]) : "r"(addr));
}
__device__ __forceinline__ void cp16(uint32_t dst_smem, const void* src) {
    asm volatile("cp.async.cg.shared.global [%0], [%1], 16;" :: "r"(dst_smem), "l"(src));
}
__device__ __forceinline__ uint32_t smem_u32(const void* p) {
    uint32_t a;
    asm("{ .reg .u64 t; cvta.to.shared.u64 t, %1; cvt.u32.u64 %0, t; }" : "=r"(a) : "l"(p));
    return a;
}
// expand 32 adjacency bits -> 32 bf16 {0,1} (64 bytes) at dst
__device__ __forceinline__ void expand32(char* dst, uint32_t w) {
    #pragma unroll
    for (int q = 0; q < 4; q++) {
        uint32_t pv[4];
        #pragma unroll
        for (int p = 0; p < 4; p++) {
            uint32_t t2 = (w >> (8 * q + 2 * p)) & 3u;
            pv[p] = ((t2 & 1u) | ((t2 & 2u) << 15)) * 0x3F80u;
        }
        *(uint4*)(dst + q * 16) = make_uint4(pv[0], pv[1], pv[2], pv[3]);
    }
}

// ---------------- GEMM: M128xN128 tile, 8 warps of 32x64, split-K, 2 CTAs/SM -----
__global__ __launch_bounds__(256, 2) void gemm_kernel() {
    extern __shared__ __align__(128) char dyn[];
    uint32_t sb = smem_u32(dyn);

    int b = blockIdx.x, tid = threadIdx.x;
    const uint32_t* bits;
    const __nv_bfloat16* Bg;
    float* raw;
    int m0, wpr, K, kbeg;
    if (b < 128) {           // dir1: top = A^T side, M=8192, K=4096, split-K=2
        int ms = b >> 1, split = b & 1;
        bits = g_bitsIU; Bg = g_B1; raw = g_raw1 + (size_t)split * I_N * 64;
        m0 = ms * 128; wpr = 128; K = U_N; kbeg = split * 2048;
    } else {                 // dir2: bot = A side, M=4096, K=8192, split-K=4
        int bb = b - 128, mb = bb >> 2, split = bb & 3;
        bits = g_bitsUI; Bg = g_B2; raw = g_raw2 + (size_t)split * U_N * 64;
        m0 = mb * 128; wpr = 256; K = I_N; kbeg = split * 2048;
    }

    int warp = tid >> 5, lane = tid & 31, g = lane >> 2, tig = lane & 3;
    int wm = warp >> 1, wn = warp & 1;           // 4x2 warp grid, 32(M) x 64(N) each

    // --- A expansion: 128 rows x 64 k; thread -> row tid>>1, 32-bit half tid&1
    int er = tid >> 1, eh = tid & 1;
    int eoff = er * PITCHB + eh * 64;
    const uint32_t* bitq = bits + (size_t)(m0 + er) * wpr + (kbeg >> 5) + eh;

    // --- B staging: 128 n x 64 k; thread covers half a row (64B = 4 cp16)
    const __nv_bfloat16* bsrc = Bg + (size_t)er * K + kbeg + eh * 32;
    int bo = eoff;                                // same geometry as A

    // --- ldmatrix address bases per buffer
    uint32_t aAddr[2], bAddr[2];
    {
        int arow = wm * 32 + (lane & 15);
        int acol = (lane >> 4) * 8;
        int brow = wn * 64 + (lane & 7) + ((lane >> 4) & 1) * 8;
        int bcol = ((lane >> 3) & 1) * 8;
        aAddr[0] = sb + OFF_A0 + arow * PITCHB + acol * 2;
        aAddr[1] = sb + OFF_A1 + arow * PITCHB + acol * 2;
        bAddr[0] = sb + OFF_B0 + brow * PITCHB + bcol * 2;
        bAddr[1] = sb + OFF_B1 + brow * PITCHB + bcol * 2;
    }

    float c[2][8][4];
    #pragma unroll
    for (int mt = 0; mt < 2; mt++)
        #pragma unroll
        for (int tn = 0; tn < 8; tn++)
            #pragma unroll
            for (int q = 0; q < 4; q++) c[mt][tn][q] = 0.f;

    // prologue: expand A(0), stage B(0), prefetch bits(1)
    expand32(dyn + OFF_A0 + eoff, bitq[0]);
    #pragma unroll
    for (int q = 0; q < 4; q++) cp16(sb + OFF_B0 + bo + q * 16, bsrc + q * 8);
    asm volatile("cp.async.commit_group;" ::: "memory");
    uint32_t wext = bitq[2];

    for (int ch = 0; ch < 32; ch++) {
        int cur = ch & 1, nx = cur ^ 1;
        if (ch < 31) {
            const __nv_bfloat16* src = bsrc + (size_t)(ch + 1) * 64;
            #pragma unroll
            for (int q = 0; q < 4; q++)
                cp16(sb + (nx ? OFF_B1 : OFF_B0) + bo + q * 16, src + q * 8);
            asm volatile("cp.async.commit_group;" ::: "memory");
            expand32(dyn + (nx ? OFF_A1 : OFF_A0) + eoff, wext);
            wext = bitq[(ch + 2 < 32 ? ch + 2 : 0) * 2];
            asm volatile("cp.async.wait_group 1;" ::: "memory");
        } else {
            asm volatile("cp.async.wait_group 0;" ::: "memory");
        }
        __syncthreads();
        #pragma unroll
        for (int s = 0; s < 4; s++) {
            uint32_t aF[2][4], bF[4][4];
            ldsm4(aF[0], aAddr[cur] + s * 32);
            ldsm4(aF[1], aAddr[cur] + s * 32 + 16 * PITCHB);
            #pragma unroll
            for (int j = 0; j < 4; j++)
                ldsm4(bF[j], bAddr[cur] + s * 32 + j * 16 * PITCHB);
            #pragma unroll
            for (int mt = 0; mt < 2; mt++)
                #pragma unroll
                for (int j = 0; j < 4; j++) {
                    mma16816(c[mt][2 * j],     aF[mt][0], aF[mt][1], aF[mt][2], aF[mt][3],
                             bF[j][0], bF[j][1]);
                    mma16816(c[mt][2 * j + 1], aF[mt][0], aF[mt][1], aF[mt][2], aF[mt][3],
                             bF[j][2], bF[j][3]);
                }
        }
        __syncthreads();
    }
    // epilogue: adjacent col pair = (hi_j, lo_j) -> sum locally, 64-wide output
    #pragma unroll
    for (int mt = 0; mt < 2; mt++)
        #pragma unroll
        for (int tn = 0; tn < 8; tn++) {
            int j = tn >> 1, hf = tn & 1;
            int row0 = m0 + wm * 32 + mt * 16 + g;
            int d = wn * 32 + j * 8 + hf * 4 + tig;
            raw[(size_t)row0 * 64 + d]       = c[mt][tn][0] + c[mt][tn][1];
            raw[(size_t)(row0 + 8) * 64 + d] = c[mt][tn][2] + c[mt][tn][3];
        }
}

// ---------------- combine: split-K sum, degree scale, concat, accumulate ----------
__global__ __launch_bounds__(256) void combine_kernel(float* out, int layer) {
    int idx = blockIdx.x * 256 + threadIdx.x;  // 786432 elems
    int row = idx >> 6, d = idx & 63;
    float v;
    if (row < I_N) {
        v = g_ri[row] * (g_raw1[(size_t)row * 64 + d] +
                         g_raw1[(size_t)(I_N + row) * 64 + d]);
    } else {
        int u = row - I_N;
        v = g_ru[u] * (g_raw2[(size_t)u * 64 + d] +
                       g_raw2[(size_t)(U_N + u) * 64 + d] +
                       g_raw2[(size_t)(2 * U_N + u) * 64 + d] +
                       g_raw2[(size_t)(3 * U_N + u) * 64 + d]);
    }
    g_x[idx] = v;
    float a = (layer == 0) ? v : (g_acc[idx] + v);
    g_acc[idx] = a;
    if (out) out[idx] = a * 0.25f;
}

// ---------------- launch ----------------
extern "C" void kernel_launch(void* const* d_in, const int* in_sizes, int n_in,
                              void* d_out, int out_size) {
    const float* x    = (const float*)d_in[0];
    const int*   edge = (const int*)d_in[1];
    float*       out  = (float*)d_out;
    cudaFuncSetAttribute(gemm_kernel, cudaFuncAttributeMaxDynamicSharedMemorySize, GSMEM_TOTAL);
    pack_kernel<<<4096, 256>>>(edge);
    scales_kernel<<<1536, 256>>>();
    for (int l = 0; l < 3; l++) {
        prep_kernel<<<192, 256>>>(x, l);
        gemm_kernel<<<256, 256, GSMEM_TOTAL>>>();
        combine_kernel<<<3072, 256>>>(l == 2 ? out : nullptr, l);
    }
}

// round 17
// speedup vs baseline: 1.6057x; 1.4675x over previous
#include <cuda_runtime.h>
#include <cuda_fp16.h>
#include <cstdint>

#define U_N 4096
#define I_N 8192
#define ROWS_T 12288
#define PITCHB 144                     // bytes per SMEM row (72 fp16)
#define ATILE (128 * PITCHB)           // 18432 B (128 m-rows x 64 k)
#define BTILE (64 * PITCHB)            // 9216 B (64 n-rows x 64 k)
#define OFF_A0 0
#define OFF_A1 ATILE
#define OFF_B0 (2 * ATILE)
#define OFF_B1 (2 * ATILE + BTILE)
#define GSMEM_TOTAL (2 * ATILE + 2 * BTILE)   // 55296 B -> 2 CTAs/SM

// ---------------- static device scratch (no runtime allocation) ----------------
__device__ __align__(256) uint32_t g_bitsUI[(size_t)U_N * 256]; // [u][i/32]
__device__ __align__(256) uint32_t g_bitsIU[(size_t)I_N * 128]; // [i][u/32]
__device__ float g_ru[U_N];
__device__ float g_ri[I_N];
// GEMM B operands, [n][k], n = dim d (0..63), fp16 single term
__device__ __align__(256) __half g_B1[(size_t)64 * U_N]; // k = user
__device__ __align__(256) __half g_B2[(size_t)64 * I_N]; // k = item
// raw GEMM outputs -> 64 dims; split-K slices
__device__ __align__(256) float g_raw1[(size_t)2 * I_N * 64];    // 2 K-splits
__device__ __align__(256) float g_raw2[(size_t)4 * U_N * 64];    // 4 K-splits
__device__ __align__(256) float g_x[(size_t)ROWS_T * 64];
__device__ __align__(256) float g_acc[(size_t)ROWS_T * 64];

// ---------------- P1: pack adjacency bits (both orientations) ----------------
__global__ __launch_bounds__(256) void pack_kernel(const int* __restrict__ edge) {
    int gw   = (blockIdx.x * 256 + threadIdx.x) >> 5;
    int lane = threadIdx.x & 31;
    int tu = gw >> 8;
    int ti = gw & 255;
    const int* base = edge + (size_t)tu * 32 * 8192 + ti * 32 + lane;
    uint32_t my = 0, uiw = 0;
    #pragma unroll 4
    for (int r = 0; r < 32; r++) {
        int val = base[(size_t)r * 8192];
        unsigned m = __ballot_sync(0xffffffffu, val != 0);
        my |= (uint32_t)(val != 0) << r;
        if (lane == r) uiw = m;
    }
    g_bitsUI[(size_t)(tu * 32 + lane) * 256 + ti] = uiw;
    g_bitsIU[(size_t)(ti * 32 + lane) * 128 + tu] = my;
}

// ---------------- P2: degrees -> rsqrt scales ----------------
__global__ __launch_bounds__(256) void scales_kernel() {
    int gw   = (blockIdx.x * 256 + threadIdx.x) >> 5;
    int lane = threadIdx.x & 31;
    int s = 0;
    if (gw < U_N) {
        const uint32_t* w = g_bitsUI + (size_t)gw * 256;
        for (int j = lane; j < 256; j += 32) s += __popc(w[j]);
        for (int o = 16; o; o >>= 1) s += __shfl_down_sync(0xffffffffu, s, o);
        if (!lane) g_ru[gw] = s ? rsqrtf((float)s) : 0.f;
    } else {
        int i = gw - U_N;
        const uint32_t* w = g_bitsIU + (size_t)i * 128;
        for (int j = lane; j < 128; j += 32) s += __popc(w[j]);
        for (int o = 16; o; o >>= 1) s += __shfl_down_sync(0xffffffffu, s, o);
        if (!lane) g_ri[i] = s ? rsqrtf((float)s) : 0.f;
    }
}

// ---------------- P3: per-layer operand prep (scale -> fp16) ----------
__global__ __launch_bounds__(256) void prep_kernel(const float* __restrict__ xin, int layer) {
    __shared__ float xs[64][65];
    int b = blockIdx.x, tid = threadIdx.x;
    const float* src = (layer == 0) ? xin : g_x;
    int k0, srow, K;
    const float* sc;
    __half* dst;
    if (b < 64) { k0 = b * 64;        srow = k0;         sc = g_ru; dst = g_B1; K = U_N; }
    else        { k0 = (b - 64) * 64; srow = U_N + k0;   sc = g_ri; dst = g_B2; K = I_N; }
    for (int i = tid; i < 4096; i += 256)
        xs[i >> 6][i & 63] = src[(size_t)(srow + (i >> 6)) * 64 + (i & 63)];
    __syncthreads();
    int ul = tid & 63, db = tid >> 6;
    float s = sc[k0 + ul];
    #pragma unroll
    for (int j = 0; j < 16; j++) {
        int d = db + j * 4;
        dst[(size_t)d * K + k0 + ul] = __float2half(s * xs[ul][d]);
    }
}

// ---------------- GEMM helpers ----------------
__device__ __forceinline__ void mma16816(float* c, uint32_t a0, uint32_t a1, uint32_t a2,
                                         uint32_t a3, uint32_t b0, uint32_t b1) {
    asm volatile(
        "mma.sync.aligned.m16n8k16.row.col.f32.f16.f16.f32 "
        "{%0,%1,%2,%3}, {%4,%5,%6,%7}, {%8,%9}, {%0,%1,%2,%3};"
        : "+f"(c[0]), "+f"(c[1]), "+f"(c[2]), "+f"(c[3])
        : "r"(a0), "r"(a1), "r"(a2), "r"(a3), "r"(b0), "r"(b1));
}
__device__ __forceinline__ void ldsm4(uint32_t* r, uint32_t addr) {
    asm volatile("ldmatrix.sync.aligned.m8n8.x4.shared.b16 {%0,%1,%2,%3}, [%4];"
                 : "=r"(r[0]), "=r"(r[1]), "=r"(r[2]), "=r"(r[3]) : "r"(addr));
}
__device__ __forceinline__ void cp16(uint32_t dst_smem, const void* src) {
    asm volatile("cp.async.cg.shared.global [%0], [%1], 16;" :: "r"(dst_smem), "l"(src));
}
__device__ __forceinline__ uint32_t smem_u32(const void* p) {
    uint32_t a;
    asm("{ .reg .u64 t; cvta.to.shared.u64 t, %1; cvt.u32.u64 %0, t; }" : "=r"(a) : "l"(p));
    return a;
}
// expand 32 adjacency bits -> 32 fp16 {0,1} (64 bytes) at dst
__device__ __forceinline__ void expand32(char* dst, uint32_t w) {
    #pragma unroll
    for (int q = 0; q < 4; q++) {
        uint32_t pv[4];
        #pragma unroll
        for (int p = 0; p < 4; p++) {
            uint32_t t2 = (w >> (8 * q + 2 * p)) & 3u;
            pv[p] = ((t2 & 1u) | ((t2 & 2u) << 15)) * 0x3C00u;   // fp16 1.0
        }
        *(uint4*)(dst + q * 16) = make_uint4(pv[0], pv[1], pv[2], pv[3]);
    }
}

// ---------------- GEMM: M128xN64 tile, 8 warps of 32x32, split-K, 2 CTAs/SM -----
__global__ __launch_bounds__(256, 2) void gemm_kernel() {
    extern __shared__ __align__(128) char dyn[];
    uint32_t sb = smem_u32(dyn);

    int b = blockIdx.x, tid = threadIdx.x;
    const uint32_t* bits;
    const __half* Bg;
    float* raw;
    int m0, wpr, K, kbeg;
    if (b < 128) {           // dir1: top = A^T side, M=8192, K=4096, split-K=2
        int ms = b >> 1, split = b & 1;
        bits = g_bitsIU; Bg = g_B1; raw = g_raw1 + (size_t)split * I_N * 64;
        m0 = ms * 128; wpr = 128; K = U_N; kbeg = split * 2048;
    } else {                 // dir2: bot = A side, M=4096, K=8192, split-K=4
        int bb = b - 128, mb = bb >> 2, split = bb & 3;
        bits = g_bitsUI; Bg = g_B2; raw = g_raw2 + (size_t)split * U_N * 64;
        m0 = mb * 128; wpr = 256; K = I_N; kbeg = split * 2048;
    }

    int warp = tid >> 5, lane = tid & 31, g = lane >> 2, tig = lane & 3;
    int wm = warp >> 1, wn = warp & 1;           // 4x2 warp grid, 32(M) x 32(N) each

    // --- A expansion: 128 rows x 64 k; thread -> row tid>>1, 32-bit half tid&1
    int er = tid >> 1, eh = tid & 1;
    int eoff = er * PITCHB + eh * 64;
    const uint32_t* bitq = bits + (size_t)(m0 + er) * wpr + (kbeg >> 5) + eh;

    // --- B staging: 64 n x 64 k fp16 = 8 KB; thread covers 32 B (2 cp16)
    int sn = tid >> 2, sq = tid & 3;
    const __half* bsrc = Bg + (size_t)sn * K + kbeg + sq * 16;
    int bo = sn * PITCHB + sq * 32;

    // --- ldmatrix address bases per buffer
    uint32_t aAddr[2], bAddr[2];
    {
        int arow = wm * 32 + (lane & 15);
        int acol = (lane >> 4) * 8;
        int brow = wn * 32 + (lane & 7) + ((lane >> 4) & 1) * 8;
        int bcol = ((lane >> 3) & 1) * 8;
        aAddr[0] = sb + OFF_A0 + arow * PITCHB + acol * 2;
        aAddr[1] = sb + OFF_A1 + arow * PITCHB + acol * 2;
        bAddr[0] = sb + OFF_B0 + brow * PITCHB + bcol * 2;
        bAddr[1] = sb + OFF_B1 + brow * PITCHB + bcol * 2;
    }

    float c[2][4][4];
    #pragma unroll
    for (int mt = 0; mt < 2; mt++)
        #pragma unroll
        for (int tn = 0; tn < 4; tn++)
            #pragma unroll
            for (int q = 0; q < 4; q++) c[mt][tn][q] = 0.f;

    // prologue: expand A(0), stage B(0), prefetch bits(1)
    expand32(dyn + OFF_A0 + eoff, bitq[0]);
    cp16(sb + OFF_B0 + bo, bsrc);
    cp16(sb + OFF_B0 + bo + 16, bsrc + 8);
    asm volatile("cp.async.commit_group;" ::: "memory");
    uint32_t wext = bitq[2];

    for (int ch = 0; ch < 32; ch++) {
        int cur = ch & 1, nx = cur ^ 1;
        if (ch < 31) {
            const __half* src = bsrc + (size_t)(ch + 1) * 64;
            cp16(sb + (nx ? OFF_B1 : OFF_B0) + bo, src);
            cp16(sb + (nx ? OFF_B1 : OFF_B0) + bo + 16, src + 8);
            asm volatile("cp.async.commit_group;" ::: "memory");
            expand32(dyn + (nx ? OFF_A1 : OFF_A0) + eoff, wext);
            wext = bitq[(ch + 2 < 32 ? ch + 2 : 0) * 2];
            asm volatile("cp.async.wait_group 1;" ::: "memory");
        } else {
            asm volatile("cp.async.wait_group 0;" ::: "memory");
        }
        __syncthreads();
        #pragma unroll
        for (int s = 0; s < 4; s++) {
            uint32_t aF[2][4], bF[2][4];
            ldsm4(aF[0], aAddr[cur] + s * 32);
            ldsm4(aF[1], aAddr[cur] + s * 32 + 16 * PITCHB);
            ldsm4(bF[0], bAddr[cur] + s * 32);
            ldsm4(bF[1], bAddr[cur] + s * 32 + 16 * PITCHB);
            #pragma unroll
            for (int mt = 0; mt < 2; mt++)
                #pragma unroll
                for (int j = 0; j < 2; j++) {
                    mma16816(c[mt][2 * j],     aF[mt][0], aF[mt][1], aF[mt][2], aF[mt][3],
                             bF[j][0], bF[j][1]);
                    mma16816(c[mt][2 * j + 1], aF[mt][0], aF[mt][1], aF[mt][2], aF[mt][3],
                             bF[j][2], bF[j][3]);
                }
        }
        __syncthreads();
    }
    // epilogue: direct store (single fp16 term, no pair-sum)
    #pragma unroll
    for (int mt = 0; mt < 2; mt++)
        #pragma unroll
        for (int tn = 0; tn < 4; tn++) {
            int row0 = m0 + wm * 32 + mt * 16 + g;
            int d = wn * 32 + (tn >> 1) * 16 + (tn & 1) * 8 + 2 * tig;
            raw[(size_t)row0 * 64 + d]           = c[mt][tn][0];
            raw[(size_t)row0 * 64 + d + 1]       = c[mt][tn][1];
            raw[(size_t)(row0 + 8) * 64 + d]     = c[mt][tn][2];
            raw[(size_t)(row0 + 8) * 64 + d + 1] = c[mt][tn][3];
        }
}

// ---------------- combine: split-K sum, degree scale, concat, accumulate ----------
__global__ __launch_bounds__(256) void combine_kernel(float* out, int layer) {
    int idx = blockIdx.x * 256 + threadIdx.x;  // 786432 elems
    int row = idx >> 6, d = idx & 63;
    float v;
    if (row < I_N) {
        v = g_ri[row] * (g_raw1[(size_t)row * 64 + d] +
                         g_raw1[(size_t)(I_N + row) * 64 + d]);
    } else {
        int u = row - I_N;
        v = g_ru[u] * (g_raw2[(size_t)u * 64 + d] +
                       g_raw2[(size_t)(U_N + u) * 64 + d] +
                       g_raw2[(size_t)(2 * U_N + u) * 64 + d] +
                       g_raw2[(size_t)(3 * U_N + u) * 64 + d]);
    }
    g_x[idx] = v;
    float a = (layer == 0) ? v : (g_acc[idx] + v);
    g_acc[idx] = a;
    if (out) out[idx] = a * 0.25f;
}

// ---------------- launch ----------------
extern "C" void kernel_launch(void* const* d_in, const int* in_sizes, int n_in,
                              void* d_out, int out_size) {
    const float* x    = (const float*)d_in[0];
    const int*   edge = (const int*)d_in[1];
    float*       out  = (float*)d_out;
    cudaFuncSetAttribute(gemm_kernel, cudaFuncAttributeMaxDynamicSharedMemorySize, GSMEM_TOTAL);
    pack_kernel<<<4096, 256>>>(edge);
    scales_kernel<<<1536, 256>>>();
    for (int l = 0; l < 3; l++) {
        prep_kernel<<<192, 256>>>(x, l);
        gemm_kernel<<<256, 256, GSMEM_TOTAL>>>();
        combine_kernel<<<3072, 256>>>(l == 2 ? out : nullptr, l);
    }
}